// round 7
// baseline (speedup 1.0000x reference)
#include <cuda_runtime.h>
#include <cuda_fp16.h>

#define N_ATOMS 8000
#define N_PAIRS 80000
#define NF 32
#define N_DIST 16
#define S (N_DIST * NF)          // 512
#define GN_EPS 1e-5f
#define HARD_CUT 6.5f

#define NB_A 500                 // A-compute blocks (16 atoms each)
#define NB_P ((N_PAIRS + 255) / 256)   // 313

// A[a][o][d] in fp16: 8.2 MB, deeply L2-resident.  Index: a*512 + o*16 + d.
__device__ __half g_Ah[N_ATOMS * S];
// Precomputed sensitivities sense[p][d]  (5 MB)
__device__ float g_sense[N_PAIRS * N_DIST];
// Segment starts: pairs for atom a are [g_seg[a], g_seg[a+1])
__device__ int g_seg[N_ATOMS + 1];

// Merged prep kernel:
//  blocks [0, NB_A):            A-compute (W staged to smem as fp16, transposed)
//  blocks [NB_A, NB_A+NB_P):    seg starts from sorted pair_first
//  blocks [NB_A+NB_P, +NB_P):   per-pair sensitivities
__global__ void __launch_bounds__(256)
kP_prep(const float* __restrict__ feat, const float* __restrict__ W,
        const int* __restrict__ pf, const float* __restrict__ dist,
        const float* __restrict__ mu, const float* __restrict__ sigma) {
    int b = blockIdx.x;
    if (b < NB_A) {
        // sw[f*528 + o*16 + d]  (pad 16 halves/row: 8-way STS conflict, aligned LDS.32x2)
        __shared__ __half sw[NF * 528];
        for (int i = threadIdx.x; i < S * NF; i += 256) {
            int f = i & 31, o = (i >> 5) & 31, d = i >> 10;
            sw[f * 528 + o * 16 + d] = __float2half_rn(W[i]);
        }
        __syncthreads();

        const int e4 = threadIdx.x & 127;        // output quad: vals e4*4 .. e4*4+3
        const int sub = threadIdx.x >> 7;        // 0/1
        const float4* feat4 = reinterpret_cast<const float4*>(feat);

#pragma unroll
        for (int pass = 0; pass < 2; pass++) {
            int a0 = b * 16 + pass * 8 + sub * 4;
            float4 acc0 = make_float4(0.f, 0.f, 0.f, 0.f);
            float4 acc1 = acc0, acc2 = acc0, acc3 = acc0;
#pragma unroll
            for (int f4 = 0; f4 < 8; f4++) {
                float fr0[4], fr1[4], fr2[4], fr3[4];
                *reinterpret_cast<float4*>(fr0) = feat4[(a0 + 0) * 8 + f4];
                *reinterpret_cast<float4*>(fr1) = feat4[(a0 + 1) * 8 + f4];
                *reinterpret_cast<float4*>(fr2) = feat4[(a0 + 2) * 8 + f4];
                *reinterpret_cast<float4*>(fr3) = feat4[(a0 + 3) * 8 + f4];
#pragma unroll
                for (int ff = 0; ff < 4; ff++) {
                    int f = f4 * 4 + ff;
                    __half2 h0 = *reinterpret_cast<const __half2*>(&sw[f * 528 + e4 * 4]);
                    __half2 h1 = *reinterpret_cast<const __half2*>(&sw[f * 528 + e4 * 4 + 2]);
                    float2 w01 = __half22float2(h0);
                    float2 w23 = __half22float2(h1);
                    acc0.x += fr0[ff] * w01.x; acc0.y += fr0[ff] * w01.y;
                    acc0.z += fr0[ff] * w23.x; acc0.w += fr0[ff] * w23.y;
                    acc1.x += fr1[ff] * w01.x; acc1.y += fr1[ff] * w01.y;
                    acc1.z += fr1[ff] * w23.x; acc1.w += fr1[ff] * w23.y;
                    acc2.x += fr2[ff] * w01.x; acc2.y += fr2[ff] * w01.y;
                    acc2.z += fr2[ff] * w23.x; acc2.w += fr2[ff] * w23.y;
                    acc3.x += fr3[ff] * w01.x; acc3.y += fr3[ff] * w01.y;
                    acc3.z += fr3[ff] * w23.x; acc3.w += fr3[ff] * w23.y;
                }
            }
            __half2* o0 = reinterpret_cast<__half2*>(g_Ah + (a0 + 0) * S + e4 * 4);
            __half2* o1 = reinterpret_cast<__half2*>(g_Ah + (a0 + 1) * S + e4 * 4);
            __half2* o2 = reinterpret_cast<__half2*>(g_Ah + (a0 + 2) * S + e4 * 4);
            __half2* o3 = reinterpret_cast<__half2*>(g_Ah + (a0 + 3) * S + e4 * 4);
            o0[0] = __floats2half2_rn(acc0.x, acc0.y); o0[1] = __floats2half2_rn(acc0.z, acc0.w);
            o1[0] = __floats2half2_rn(acc1.x, acc1.y); o1[1] = __floats2half2_rn(acc1.z, acc1.w);
            o2[0] = __floats2half2_rn(acc2.x, acc2.y); o2[1] = __floats2half2_rn(acc2.z, acc2.w);
            o3[0] = __floats2half2_rn(acc3.x, acc3.y); o3[1] = __floats2half2_rn(acc3.z, acc3.w);
        }
    } else if (b < NB_A + NB_P) {
        int p = (b - NB_A) * 256 + threadIdx.x;
        if (p >= N_PAIRS) return;
        int cur = pf[p];
        int prev = (p == 0) ? -1 : pf[p - 1];
        for (int x = prev + 1; x <= cur; x++) g_seg[x] = p;
        if (p == N_PAIRS - 1)
            for (int x = cur + 1; x <= N_ATOMS; x++) g_seg[x] = N_PAIRS;
    } else {
        int p = (b - NB_A - NB_P) * 256 + threadIdx.x;
        if (p >= N_PAIRS) return;
        float dd  = dist[p];
        float inv = 1.f / dd;
        float c   = __cosf(dd * (float)(3.14159265358979323846 / (2.0 * 6.5)));
        float cut = (dd < HARD_CUT) ? c * c : 0.f;
        float4* outp = reinterpret_cast<float4*>(g_sense + p * N_DIST);
#pragma unroll
        for (int q = 0; q < 4; q++) {
            float4 r;
            float z0 = (inv - mu[4 * q + 0]) / sigma[4 * q + 0];
            float z1 = (inv - mu[4 * q + 1]) / sigma[4 * q + 1];
            float z2 = (inv - mu[4 * q + 2]) / sigma[4 * q + 2];
            float z3 = (inv - mu[4 * q + 3]) / sigma[4 * q + 3];
            r.x = __expf(-0.5f * z0 * z0) * cut;
            r.y = __expf(-0.5f * z1 * z1) * cut;
            r.z = __expf(-0.5f * z2 * z2) * cut;
            r.w = __expf(-0.5f * z3 * z3) * cut;
            outp[q] = r;
        }
    }
}

// Per-pair body: lane = output channel o; 2 LDG.128 of halves + 4 uniform float4.
__device__ __forceinline__ void pair_body(int p, int lane, const int* __restrict__ ps,
                                          const float* __restrict__ rhats,
                                          float& tf0, float& tf1, float& tf2, float& tf3) {
    int j = ps[p];
    float4 r = *reinterpret_cast<const float4*>(rhats + 4 * p);
    const float4* Ap = reinterpret_cast<const float4*>(g_Ah + j * S + lane * N_DIST);
    float4 ha = Ap[0];          // halves d0..d7
    float4 hb = Ap[1];          // halves d8..d15
    const float4* sp = reinterpret_cast<const float4*>(g_sense + p * N_DIST);
    float4 s0 = sp[0], s1 = sp[1], s2 = sp[2], s3 = sp[3];

    const __half2* h = reinterpret_cast<const __half2*>(&ha);
    float2 f0 = __half22float2(h[0]);
    float2 f1 = __half22float2(h[1]);
    float2 f2 = __half22float2(h[2]);
    float2 f3 = __half22float2(h[3]);
    const __half2* g = reinterpret_cast<const __half2*>(&hb);
    float2 f4 = __half22float2(g[0]);
    float2 f5 = __half22float2(g[1]);
    float2 f6 = __half22float2(g[2]);
    float2 f7 = __half22float2(g[3]);

    float v = s0.x * f0.x + s0.y * f0.y + s0.z * f1.x + s0.w * f1.y
            + s1.x * f2.x + s1.y * f2.y + s1.z * f3.x + s1.w * f3.y
            + s2.x * f4.x + s2.y * f4.y + s2.z * f5.x + s2.w * f5.y
            + s3.x * f6.x + s3.y * f6.y + s3.z * f7.x + s3.w * f7.y;

    tf0 += r.x * v; tf1 += r.y * v; tf2 += r.z * v; tf3 += r.w * v;
}

__global__ void __launch_bounds__(128)
k2_atoms(const float* __restrict__ feat,
         const float* __restrict__ rhats,
         const float* __restrict__ selfW,
         const float* __restrict__ selfB,
         const float* __restrict__ mixW,
         const float* __restrict__ gnw,
         const float* __restrict__ gnb,
         const int* __restrict__ ps,
         float* __restrict__ out) {
    const unsigned FULL = 0xffffffffu;
    int warp = (blockIdx.x * blockDim.x + threadIdx.x) >> 5;
    int lane = threadIdx.x & 31;
    if (warp >= N_ATOMS) return;
    const int a = warp;

    const int segs = g_seg[a];
    const int sege = g_seg[a + 1];

    float tf0 = 0.f, tf1 = 0.f, tf2 = 0.f, tf3 = 0.f;
    float u0 = 0.f, u1 = 0.f, u2 = 0.f, u3 = 0.f;

    int p = segs;
    for (; p + 2 <= sege; p += 2) {
        pair_body(p,     lane, ps, rhats, tf0, tf1, tf2, tf3);
        pair_body(p + 1, lane, ps, rhats, u0, u1, u2, u3);
    }
    if (p < sege) pair_body(p, lane, ps, rhats, tf0, tf1, tf2, tf3);
    tf0 += u0; tf1 += u1; tf2 += u2; tf3 += u3;

    // invariants: x0 = l=0 scalar, x1 = |l=1 vector|^2
    float x0 = tf0;
    float x1 = tf1 * tf1 + tf2 * tf2 + tf3 * tf3;

    // GroupNorm: each group == the 32 lanes of this warp
    float s0 = x0, s1 = x1;
#pragma unroll
    for (int off = 16; off; off >>= 1) {
        s0 += __shfl_xor_sync(FULL, s0, off);
        s1 += __shfl_xor_sync(FULL, s1, off);
    }
    float m0 = s0 * (1.f / 32.f), m1 = s1 * (1.f / 32.f);
    float d0 = x0 - m0, d1 = x1 - m1;
    float q0 = d0 * d0, q1 = d1 * d1;
#pragma unroll
    for (int off = 16; off; off >>= 1) {
        q0 += __shfl_xor_sync(FULL, q0, off);
        q1 += __shfl_xor_sync(FULL, q1, off);
    }
    float var0 = q0 * (1.f / 32.f), var1 = q1 * (1.f / 32.f);
    float xn0 = d0 * rsqrtf(var0 + GN_EPS) * gnw[lane]      + gnb[lane];
    float xn1 = d1 * rsqrtf(var1 + GN_EPS) * gnw[32 + lane] + gnb[32 + lane];

    // mixing: out[o2] = sum_o xn0(o)*Mw[(2o)*32+o2] + xn1(o)*Mw[(2o+1)*32+o2]
    float acc = 0.f;
#pragma unroll
    for (int o = 0; o < 32; o++) {
        float a0 = __shfl_sync(FULL, xn0, o);
        float a1 = __shfl_sync(FULL, xn1, o);
        acc += a0 * mixW[(o * 2 + 0) * 32 + lane]
             + a1 * mixW[(o * 2 + 1) * 32 + lane];
    }

    // self interaction: sp[o] = b[o] + sum_f feat[a,f] * selfW[o,f]
    const float* frow = feat + a * NF;
    const float* wrow = selfW + lane * NF;
    float sp = selfB[lane];
#pragma unroll
    for (int f = 0; f < NF; f++) sp += frow[f] * wrow[f];

    out[a * NF + lane] = acc + sp;
}

extern "C" void kernel_launch(void* const* d_in, const int* in_sizes, int n_in,
                              void* d_out, int out_size) {
    const float* in_features = (const float*)d_in[0];
    const float* tensor_rhats = (const float*)d_in[1];
    const float* dist_pairs   = (const float*)d_in[2];
    const float* int_weights  = (const float*)d_in[3];
    const float* selfint_w    = (const float*)d_in[4];
    const float* selfint_b    = (const float*)d_in[5];
    const float* mixing_w     = (const float*)d_in[6];
    const float* gn_weight    = (const float*)d_in[7];
    const float* gn_bias      = (const float*)d_in[8];
    const float* sens_mu      = (const float*)d_in[9];
    const float* sens_sigma   = (const float*)d_in[10];
    const int*   pair_first   = (const int*)d_in[11];
    const int*   pair_second  = (const int*)d_in[12];
    float* out = (float*)d_out;

    kP_prep<<<NB_A + 2 * NB_P, 256>>>(in_features, int_weights, pair_first,
                                      dist_pairs, sens_mu, sens_sigma);
    {
        int threads = 128;                 // 4 warps/block, 1 warp per atom
        int blocks = (N_ATOMS * 32 + threads - 1) / threads;
        k2_atoms<<<blocks, threads>>>(in_features, tensor_rhats,
                                      selfint_w, selfint_b, mixing_w,
                                      gn_weight, gn_bias, pair_second, out);
    }
}

// round 9
// speedup vs baseline: 1.1159x; 1.1159x over previous
#include <cuda_runtime.h>
#include <cuda_fp16.h>

#define N_ATOMS 8000
#define N_PAIRS 80000
#define NF 32
#define N_DIST 16
#define S (N_DIST * NF)          // 512
#define GN_EPS 1e-5f
#define HARD_CUT 6.5f

// A[a][o][d] in fp16: 8.2 MB, deeply L2-resident.  Half index: a*512 + o*16 + d.
__device__ __half g_Ah[N_ATOMS * S];
// Transposed weights: Wt2[f][o*16+d] = W[d][o][f]  (64 KB fp32)
__device__ float g_Wt2[NF * S];
// Precomputed sensitivities, fp16: senseh[p*16 + d]  (2.5 MB)
__device__ __half g_senseh[N_PAIRS * N_DIST];
// Segment starts: pairs for atom a are [g_seg[a], g_seg[a+1])
__device__ int g_seg[N_ATOMS + 1];

// Merged light prep (R5 structure):
//  blocks [0,64): transpose W -> Wt2;  [64,377): seg;  [377,690): sense (fp16)
__global__ void k0_prep(const float* __restrict__ W, const int* __restrict__ pf,
                        const float* __restrict__ dist,
                        const float* __restrict__ mu, const float* __restrict__ sigma) {
    int b = blockIdx.x;
    if (b < 64) {
        int idx = b * 256 + threadIdx.x;            // over S*NF = 16384
        int d = idx & 15;
        int o = (idx >> 4) & 31;
        int f = idx >> 9;
        g_Wt2[idx] = W[(d * NF + o) * NF + f];
    } else if (b < 64 + 313) {
        int p = (b - 64) * 256 + threadIdx.x;
        if (p >= N_PAIRS) return;
        int cur = pf[p];
        int prev = (p == 0) ? -1 : pf[p - 1];
        for (int x = prev + 1; x <= cur; x++) g_seg[x] = p;
        if (p == N_PAIRS - 1)
            for (int x = cur + 1; x <= N_ATOMS; x++) g_seg[x] = N_PAIRS;
    } else {
        int p = (b - 377) * 256 + threadIdx.x;
        if (p >= N_PAIRS) return;
        float dd  = dist[p];
        float inv = 1.f / dd;
        float c   = __cosf(dd * (float)(3.14159265358979323846 / (2.0 * 6.5)));
        float cut = (dd < HARD_CUT) ? c * c : 0.f;
        __half2* outp = reinterpret_cast<__half2*>(g_senseh + p * N_DIST);
#pragma unroll
        for (int q = 0; q < 4; q++) {
            float z0 = (inv - mu[4 * q + 0]) / sigma[4 * q + 0];
            float z1 = (inv - mu[4 * q + 1]) / sigma[4 * q + 1];
            float z2 = (inv - mu[4 * q + 2]) / sigma[4 * q + 2];
            float z3 = (inv - mu[4 * q + 3]) / sigma[4 * q + 3];
            float r0 = __expf(-0.5f * z0 * z0) * cut;
            float r1 = __expf(-0.5f * z1 * z1) * cut;
            float r2 = __expf(-0.5f * z2 * z2) * cut;
            float r3 = __expf(-0.5f * z3 * z3) * cut;
            outp[q * 2 + 0] = __floats2half2_rn(r0, r1);
            outp[q * 2 + 1] = __floats2half2_rn(r2, r3);
        }
    }
}

// k1: A[a][o][d] = sum_f feat[a,f] * W[d,o,f], 4 atoms per thread (R5 version).
__global__ void __launch_bounds__(256)
k1_precompute(const float* __restrict__ feat) {
    int idx = blockIdx.x * blockDim.x + threadIdx.x;   // over (N_ATOMS/4)*128
    if (idx >= (N_ATOMS / 4) * 128) return;
    int a0 = (idx >> 7) * 4;
    int e4 = idx & 127;
    const float4* feat4 = reinterpret_cast<const float4*>(feat);
    const float4* Wt4   = reinterpret_cast<const float4*>(g_Wt2);
    float4 acc0 = make_float4(0.f, 0.f, 0.f, 0.f);
    float4 acc1 = acc0, acc2 = acc0, acc3 = acc0;
#pragma unroll
    for (int f4 = 0; f4 < 8; f4++) {
        float4 w0 = Wt4[(4 * f4 + 0) * 128 + e4];
        float4 w1 = Wt4[(4 * f4 + 1) * 128 + e4];
        float4 w2 = Wt4[(4 * f4 + 2) * 128 + e4];
        float4 w3 = Wt4[(4 * f4 + 3) * 128 + e4];
        float4 fr0 = feat4[(a0 + 0) * 8 + f4];
        float4 fr1 = feat4[(a0 + 1) * 8 + f4];
        float4 fr2 = feat4[(a0 + 2) * 8 + f4];
        float4 fr3 = feat4[(a0 + 3) * 8 + f4];
        acc0.x += fr0.x * w0.x + fr0.y * w1.x + fr0.z * w2.x + fr0.w * w3.x;
        acc0.y += fr0.x * w0.y + fr0.y * w1.y + fr0.z * w2.y + fr0.w * w3.y;
        acc0.z += fr0.x * w0.z + fr0.y * w1.z + fr0.z * w2.z + fr0.w * w3.z;
        acc0.w += fr0.x * w0.w + fr0.y * w1.w + fr0.z * w2.w + fr0.w * w3.w;
        acc1.x += fr1.x * w0.x + fr1.y * w1.x + fr1.z * w2.x + fr1.w * w3.x;
        acc1.y += fr1.x * w0.y + fr1.y * w1.y + fr1.z * w2.y + fr1.w * w3.y;
        acc1.z += fr1.x * w0.z + fr1.y * w1.z + fr1.z * w2.z + fr1.w * w3.z;
        acc1.w += fr1.x * w0.w + fr1.y * w1.w + fr1.z * w2.w + fr1.w * w3.w;
        acc2.x += fr2.x * w0.x + fr2.y * w1.x + fr2.z * w2.x + fr2.w * w3.x;
        acc2.y += fr2.x * w0.y + fr2.y * w1.y + fr2.z * w2.y + fr2.w * w3.y;
        acc2.z += fr2.x * w0.z + fr2.y * w1.z + fr2.z * w2.z + fr2.w * w3.z;
        acc2.w += fr2.x * w0.w + fr2.y * w1.w + fr2.z * w2.w + fr2.w * w3.w;
        acc3.x += fr3.x * w0.x + fr3.y * w1.x + fr3.z * w2.x + fr3.w * w3.x;
        acc3.y += fr3.x * w0.y + fr3.y * w1.y + fr3.z * w2.y + fr3.w * w3.y;
        acc3.z += fr3.x * w0.z + fr3.y * w1.z + fr3.z * w2.z + fr3.w * w3.z;
        acc3.w += fr3.x * w0.w + fr3.y * w1.w + fr3.z * w2.w + fr3.w * w3.w;
    }
    __half2* o0 = reinterpret_cast<__half2*>(g_Ah + (a0 + 0) * S + e4 * 4);
    __half2* o1 = reinterpret_cast<__half2*>(g_Ah + (a0 + 1) * S + e4 * 4);
    __half2* o2 = reinterpret_cast<__half2*>(g_Ah + (a0 + 2) * S + e4 * 4);
    __half2* o3 = reinterpret_cast<__half2*>(g_Ah + (a0 + 3) * S + e4 * 4);
    o0[0] = __floats2half2_rn(acc0.x, acc0.y); o0[1] = __floats2half2_rn(acc0.z, acc0.w);
    o1[0] = __floats2half2_rn(acc1.x, acc1.y); o1[1] = __floats2half2_rn(acc1.z, acc1.w);
    o2[0] = __floats2half2_rn(acc2.x, acc2.y); o2[1] = __floats2half2_rn(acc2.z, acc2.w);
    o3[0] = __floats2half2_rn(acc3.x, acc3.y); o3[1] = __floats2half2_rn(acc3.z, acc3.w);
}

// Contiguous gather + butterfly.  Lane L loads row bytes [L*16, L*16+16) and
// [512+L*16, ...): 4 wavefronts per LDG instead of 8.  Lane holds d-half
// (L&1)*8.. of channel L>>1 (LDG1) and 16+(L>>1) (LDG2).
__device__ __forceinline__ void pair_body(int p, int lane, const int* __restrict__ ps,
                                          const float* __restrict__ rhats,
                                          float& tf0, float& tf1, float& tf2, float& tf3) {
    const unsigned FULL = 0xffffffffu;
    int j = ps[p];
    float4 r = *reinterpret_cast<const float4*>(rhats + 4 * p);
    const float4* Ap = reinterpret_cast<const float4*>(g_Ah + j * S);
    float4 ha = Ap[lane];        // contiguous: lanes cover first 512B
    float4 hb = Ap[32 + lane];   // second 512B
    // sense: lane picks its own d-half (8 halves = one float4)
    float4 sh = reinterpret_cast<const float4*>(g_senseh + p * N_DIST)[lane & 1];

    const __half2* sv = reinterpret_cast<const __half2*>(&sh);
    float2 s0 = __half22float2(sv[0]);
    float2 s1 = __half22float2(sv[1]);
    float2 s2 = __half22float2(sv[2]);
    float2 s3 = __half22float2(sv[3]);

    const __half2* av = reinterpret_cast<const __half2*>(&ha);
    float2 a0 = __half22float2(av[0]);
    float2 a1 = __half22float2(av[1]);
    float2 a2 = __half22float2(av[2]);
    float2 a3 = __half22float2(av[3]);
    const __half2* bv = reinterpret_cast<const __half2*>(&hb);
    float2 b0 = __half22float2(bv[0]);
    float2 b1 = __half22float2(bv[1]);
    float2 b2 = __half22float2(bv[2]);
    float2 b3 = __half22float2(bv[3]);

    float p1 = s0.x * a0.x + s0.y * a0.y + s1.x * a1.x + s1.y * a1.y
             + s2.x * a2.x + s2.y * a2.y + s3.x * a3.x + s3.y * a3.y;
    float p2 = s0.x * b0.x + s0.y * b0.y + s1.x * b1.x + s1.y * b1.y
             + s2.x * b2.x + s2.y * b2.y + s3.x * b3.x + s3.y * b3.y;

    float v1 = p1 + __shfl_xor_sync(FULL, p1, 1);   // lanes 2c,2c+1: v[c]
    float v2 = p2 + __shfl_xor_sync(FULL, p2, 1);   // lanes 2c,2c+1: v[16+c]
    int src = (2 * lane) & 31;
    float w1 = __shfl_sync(FULL, v1, src);
    float w2 = __shfl_sync(FULL, v2, src);
    float v = (lane < 16) ? w1 : w2;                // v[lane]

    tf0 += r.x * v; tf1 += r.y * v; tf2 += r.z * v; tf3 += r.w * v;
}

__global__ void __launch_bounds__(128)
k2_atoms(const float* __restrict__ feat,
         const float* __restrict__ rhats,
         const float* __restrict__ selfW,
         const float* __restrict__ selfB,
         const float* __restrict__ mixW,
         const float* __restrict__ gnw,
         const float* __restrict__ gnb,
         const int* __restrict__ ps,
         float* __restrict__ out) {
    const unsigned FULL = 0xffffffffu;
    int warp = (blockIdx.x * blockDim.x + threadIdx.x) >> 5;
    int lane = threadIdx.x & 31;
    if (warp >= N_ATOMS) return;
    const int a = warp;

    const int segs = g_seg[a];
    const int sege = g_seg[a + 1];

    float tf0 = 0.f, tf1 = 0.f, tf2 = 0.f, tf3 = 0.f;
    float u0 = 0.f, u1 = 0.f, u2 = 0.f, u3 = 0.f;

    int p = segs;
    for (; p + 2 <= sege; p += 2) {
        pair_body(p,     lane, ps, rhats, tf0, tf1, tf2, tf3);
        pair_body(p + 1, lane, ps, rhats, u0, u1, u2, u3);
    }
    if (p < sege) pair_body(p, lane, ps, rhats, tf0, tf1, tf2, tf3);
    tf0 += u0; tf1 += u1; tf2 += u2; tf3 += u3;

    // invariants: x0 = l=0 scalar, x1 = |l=1 vector|^2
    float x0 = tf0;
    float x1 = tf1 * tf1 + tf2 * tf2 + tf3 * tf3;

    // GroupNorm: each group == the 32 lanes of this warp
    float s0 = x0, s1 = x1;
#pragma unroll
    for (int off = 16; off; off >>= 1) {
        s0 += __shfl_xor_sync(FULL, s0, off);
        s1 += __shfl_xor_sync(FULL, s1, off);
    }
    float m0 = s0 * (1.f / 32.f), m1 = s1 * (1.f / 32.f);
    float d0 = x0 - m0, d1 = x1 - m1;
    float q0 = d0 * d0, q1 = d1 * d1;
#pragma unroll
    for (int off = 16; off; off >>= 1) {
        q0 += __shfl_xor_sync(FULL, q0, off);
        q1 += __shfl_xor_sync(FULL, q1, off);
    }
    float var0 = q0 * (1.f / 32.f), var1 = q1 * (1.f / 32.f);
    float xn0 = d0 * rsqrtf(var0 + GN_EPS) * gnw[lane]      + gnb[lane];
    float xn1 = d1 * rsqrtf(var1 + GN_EPS) * gnw[32 + lane] + gnb[32 + lane];

    // mixing
    float acc = 0.f;
#pragma unroll
    for (int o = 0; o < 32; o++) {
        float a0 = __shfl_sync(FULL, xn0, o);
        float a1 = __shfl_sync(FULL, xn1, o);
        acc += a0 * mixW[(o * 2 + 0) * 32 + lane]
             + a1 * mixW[(o * 2 + 1) * 32 + lane];
    }

    // self interaction
    const float* frow = feat + a * NF;
    const float* wrow = selfW + lane * NF;
    float sp = selfB[lane];
#pragma unroll
    for (int f = 0; f < NF; f++) sp += frow[f] * wrow[f];

    out[a * NF + lane] = acc + sp;
}

extern "C" void kernel_launch(void* const* d_in, const int* in_sizes, int n_in,
                              void* d_out, int out_size) {
    const float* in_features = (const float*)d_in[0];
    const float* tensor_rhats = (const float*)d_in[1];
    const float* dist_pairs   = (const float*)d_in[2];
    const float* int_weights  = (const float*)d_in[3];
    const float* selfint_w    = (const float*)d_in[4];
    const float* selfint_b    = (const float*)d_in[5];
    const float* mixing_w     = (const float*)d_in[6];
    const float* gn_weight    = (const float*)d_in[7];
    const float* gn_bias      = (const float*)d_in[8];
    const float* sens_mu      = (const float*)d_in[9];
    const float* sens_sigma   = (const float*)d_in[10];
    const int*   pair_first   = (const int*)d_in[11];
    const int*   pair_second  = (const int*)d_in[12];
    float* out = (float*)d_out;

    k0_prep<<<64 + 2 * ((N_PAIRS + 255) / 256), 256>>>(int_weights, pair_first,
                                                       dist_pairs, sens_mu, sens_sigma);
    k1_precompute<<<((N_ATOMS / 4) * 128 + 255) / 256, 256>>>(in_features);
    {
        int threads = 128;                 // 4 warps/block, 1 warp per atom
        int blocks = (N_ATOMS * 32 + threads - 1) / threads;
        k2_atoms<<<blocks, threads>>>(in_features, tensor_rhats,
                                      selfint_w, selfint_b, mixing_w,
                                      gn_weight, gn_bias, pair_second, out);
    }
}

// round 13
// speedup vs baseline: 1.2176x; 1.0911x over previous
#include <cuda_runtime.h>
#include <cuda_fp16.h>

#define N_ATOMS 8000
#define N_PAIRS 80000
#define NF 32
#define N_DIST 16
#define S (N_DIST * NF)          // 512
#define GN_EPS 1e-5f
#define HARD_CUT 6.5f

// A[a][o][d] in fp16: 8.2 MB, L2-resident.  Half index: a*512 + o*16 + d.
__device__ __half g_Ah[N_ATOMS * S];
// Transposed weights: Wt2[f][o*16+d] = W[d][o][f]  (64 KB fp32)
__device__ float g_Wt2[NF * S];
// Precomputed sensitivities, fp16: senseh[p*16 + d]  (2.5 MB)
__device__ __half g_senseh[N_PAIRS * N_DIST];
// Per-pair channel vector v[p][o]  (10 MB fp32)
__device__ float g_v[N_PAIRS * NF];
// Segment starts: pairs for atom a are [g_seg[a], g_seg[a+1])
__device__ int g_seg[N_ATOMS + 1];

// Merged light prep:
//  blocks [0,64): transpose W -> Wt2;  [64,377): seg;  [377,690): sense (fp16)
__global__ void k0_prep(const float* __restrict__ W, const int* __restrict__ pf,
                        const float* __restrict__ dist,
                        const float* __restrict__ mu, const float* __restrict__ sigma) {
    int b = blockIdx.x;
    if (b < 64) {
        int idx = b * 256 + threadIdx.x;            // over S*NF = 16384
        int d = idx & 15;
        int o = (idx >> 4) & 31;
        int f = idx >> 9;
        g_Wt2[idx] = W[(d * NF + o) * NF + f];
    } else if (b < 64 + 313) {
        int p = (b - 64) * 256 + threadIdx.x;
        if (p >= N_PAIRS) return;
        int cur = pf[p];
        int prev = (p == 0) ? -1 : pf[p - 1];
        for (int x = prev + 1; x <= cur; x++) g_seg[x] = p;
        if (p == N_PAIRS - 1)
            for (int x = cur + 1; x <= N_ATOMS; x++) g_seg[x] = N_PAIRS;
    } else {
        int p = (b - 377) * 256 + threadIdx.x;
        if (p >= N_PAIRS) return;
        float dd  = dist[p];
        float inv = 1.f / dd;
        float c   = __cosf(dd * (float)(3.14159265358979323846 / (2.0 * 6.5)));
        float cut = (dd < HARD_CUT) ? c * c : 0.f;
        __half2* outp = reinterpret_cast<__half2*>(g_senseh + p * N_DIST);
#pragma unroll
        for (int q = 0; q < 4; q++) {
            float z0 = (inv - mu[4 * q + 0]) / sigma[4 * q + 0];
            float z1 = (inv - mu[4 * q + 1]) / sigma[4 * q + 1];
            float z2 = (inv - mu[4 * q + 2]) / sigma[4 * q + 2];
            float z3 = (inv - mu[4 * q + 3]) / sigma[4 * q + 3];
            float r0 = __expf(-0.5f * z0 * z0) * cut;
            float r1 = __expf(-0.5f * z1 * z1) * cut;
            float r2 = __expf(-0.5f * z2 * z2) * cut;
            float r3 = __expf(-0.5f * z3 * z3) * cut;
            outp[q * 2 + 0] = __floats2half2_rn(r0, r1);
            outp[q * 2 + 1] = __floats2half2_rn(r2, r3);
        }
    }
}

// k1: A[a][o][d] = sum_f feat[a,f] * W[d,o,f], 4 atoms per thread.
__global__ void __launch_bounds__(256)
k1_precompute(const float* __restrict__ feat) {
    int idx = blockIdx.x * blockDim.x + threadIdx.x;   // over (N_ATOMS/4)*128
    if (idx >= (N_ATOMS / 4) * 128) return;
    int a0 = (idx >> 7) * 4;
    int e4 = idx & 127;
    const float4* feat4 = reinterpret_cast<const float4*>(feat);
    const float4* Wt4   = reinterpret_cast<const float4*>(g_Wt2);
    float4 acc0 = make_float4(0.f, 0.f, 0.f, 0.f);
    float4 acc1 = acc0, acc2 = acc0, acc3 = acc0;
#pragma unroll
    for (int f4 = 0; f4 < 8; f4++) {
        float4 w0 = Wt4[(4 * f4 + 0) * 128 + e4];
        float4 w1 = Wt4[(4 * f4 + 1) * 128 + e4];
        float4 w2 = Wt4[(4 * f4 + 2) * 128 + e4];
        float4 w3 = Wt4[(4 * f4 + 3) * 128 + e4];
        float4 fr0 = feat4[(a0 + 0) * 8 + f4];
        float4 fr1 = feat4[(a0 + 1) * 8 + f4];
        float4 fr2 = feat4[(a0 + 2) * 8 + f4];
        float4 fr3 = feat4[(a0 + 3) * 8 + f4];
        acc0.x += fr0.x * w0.x + fr0.y * w1.x + fr0.z * w2.x + fr0.w * w3.x;
        acc0.y += fr0.x * w0.y + fr0.y * w1.y + fr0.z * w2.y + fr0.w * w3.y;
        acc0.z += fr0.x * w0.z + fr0.y * w1.z + fr0.z * w2.z + fr0.w * w3.z;
        acc0.w += fr0.x * w0.w + fr0.y * w1.w + fr0.z * w2.w + fr0.w * w3.w;
        acc1.x += fr1.x * w0.x + fr1.y * w1.x + fr1.z * w2.x + fr1.w * w3.x;
        acc1.y += fr1.x * w0.y + fr1.y * w1.y + fr1.z * w2.y + fr1.w * w3.y;
        acc1.z += fr1.x * w0.z + fr1.y * w1.z + fr1.z * w2.z + fr1.w * w3.z;
        acc1.w += fr1.x * w0.w + fr1.y * w1.w + fr1.z * w2.w + fr1.w * w3.w;
        acc2.x += fr2.x * w0.x + fr2.y * w1.x + fr2.z * w2.x + fr2.w * w3.x;
        acc2.y += fr2.x * w0.y + fr2.y * w1.y + fr2.z * w2.y + fr2.w * w3.y;
        acc2.z += fr2.x * w0.z + fr2.y * w1.z + fr2.z * w2.z + fr2.w * w3.z;
        acc2.w += fr2.x * w0.w + fr2.y * w1.w + fr2.z * w2.w + fr2.w * w3.w;
        acc3.x += fr3.x * w0.x + fr3.y * w1.x + fr3.z * w2.x + fr3.w * w3.x;
        acc3.y += fr3.x * w0.y + fr3.y * w1.y + fr3.z * w2.y + fr3.w * w3.y;
        acc3.z += fr3.x * w0.z + fr3.y * w1.z + fr3.z * w2.z + fr3.w * w3.z;
        acc3.w += fr3.x * w0.w + fr3.y * w1.w + fr3.z * w2.w + fr3.w * w3.w;
    }
    __half2* o0 = reinterpret_cast<__half2*>(g_Ah + (a0 + 0) * S + e4 * 4);
    __half2* o1 = reinterpret_cast<__half2*>(g_Ah + (a0 + 1) * S + e4 * 4);
    __half2* o2 = reinterpret_cast<__half2*>(g_Ah + (a0 + 2) * S + e4 * 4);
    __half2* o3 = reinterpret_cast<__half2*>(g_Ah + (a0 + 3) * S + e4 * 4);
    o0[0] = __floats2half2_rn(acc0.x, acc0.y); o0[1] = __floats2half2_rn(acc0.z, acc0.w);
    o1[0] = __floats2half2_rn(acc1.x, acc1.y); o1[1] = __floats2half2_rn(acc1.z, acc1.w);
    o2[0] = __floats2half2_rn(acc2.x, acc2.y); o2[1] = __floats2half2_rn(acc2.z, acc2.w);
    o3[0] = __floats2half2_rn(acc3.x, acc3.y); o3[1] = __floats2half2_rn(acc3.z, acc3.w);
}

// kv: one warp per pair.  v[p][o] = sum_d sense[p,d] * A[j][o][d].
// Contiguous gather + butterfly, ending in a coalesced store.
__global__ void __launch_bounds__(256)
kv_pairs(const int* __restrict__ ps) {
    const unsigned FULL = 0xffffffffu;
    int p = (blockIdx.x * blockDim.x + threadIdx.x) >> 5;
    int lane = threadIdx.x & 31;
    if (p >= N_PAIRS) return;

    int j = ps[p];                                   // uniform broadcast
    const float4* Ap = reinterpret_cast<const float4*>(g_Ah + j * S);
    float4 ha = Ap[lane];        // lanes cover first 512B contiguously
    float4 hb = Ap[32 + lane];   // second 512B
    float4 sh = reinterpret_cast<const float4*>(g_senseh + p * N_DIST)[lane & 1];

    const __half2* sv = reinterpret_cast<const __half2*>(&sh);
    float2 s0 = __half22float2(sv[0]);
    float2 s1 = __half22float2(sv[1]);
    float2 s2 = __half22float2(sv[2]);
    float2 s3 = __half22float2(sv[3]);

    const __half2* av = reinterpret_cast<const __half2*>(&ha);
    float2 a0 = __half22float2(av[0]);
    float2 a1 = __half22float2(av[1]);
    float2 a2 = __half22float2(av[2]);
    float2 a3 = __half22float2(av[3]);
    const __half2* bv = reinterpret_cast<const __half2*>(&hb);
    float2 b0 = __half22float2(bv[0]);
    float2 b1 = __half22float2(bv[1]);
    float2 b2 = __half22float2(bv[2]);
    float2 b3 = __half22float2(bv[3]);

    float p1 = s0.x * a0.x + s0.y * a0.y + s1.x * a1.x + s1.y * a1.y
             + s2.x * a2.x + s2.y * a2.y + s3.x * a3.x + s3.y * a3.y;
    float p2 = s0.x * b0.x + s0.y * b0.y + s1.x * b1.x + s1.y * b1.y
             + s2.x * b2.x + s2.y * b2.y + s3.x * b3.x + s3.y * b3.y;

    float v1 = p1 + __shfl_xor_sync(FULL, p1, 1);    // lanes 2c,2c+1: v[c]
    float v2 = p2 + __shfl_xor_sync(FULL, p2, 1);    // lanes 2c,2c+1: v[16+c]
    int src = (2 * lane) & 31;
    float w1 = __shfl_sync(FULL, v1, src);
    float w2 = __shfl_sync(FULL, v2, src);
    float v = (lane < 16) ? w1 : w2;                 // v[lane]

    g_v[p * NF + lane] = v;                          // coalesced 128B store
}

// katoms: warp per atom.  Segment loop reads v[p][lane] contiguous, independent.
__global__ void __launch_bounds__(128)
k2_atoms(const float* __restrict__ feat,
         const float* __restrict__ rhats,
         const float* __restrict__ selfW,
         const float* __restrict__ selfB,
         const float* __restrict__ mixW,
         const float* __restrict__ gnw,
         const float* __restrict__ gnb,
         float* __restrict__ out) {
    const unsigned FULL = 0xffffffffu;
    int warp = (blockIdx.x * blockDim.x + threadIdx.x) >> 5;
    int lane = threadIdx.x & 31;
    if (warp >= N_ATOMS) return;
    const int a = warp;

    const int segs = g_seg[a];
    const int sege = g_seg[a + 1];

    float tf0 = 0.f, tf1 = 0.f, tf2 = 0.f, tf3 = 0.f;
    float u0 = 0.f, u1 = 0.f, u2 = 0.f, u3 = 0.f;

    int p = segs;
    for (; p + 4 <= sege; p += 4) {
        float4 r0 = *reinterpret_cast<const float4*>(rhats + 4 * (p + 0));
        float4 r1 = *reinterpret_cast<const float4*>(rhats + 4 * (p + 1));
        float4 r2 = *reinterpret_cast<const float4*>(rhats + 4 * (p + 2));
        float4 r3 = *reinterpret_cast<const float4*>(rhats + 4 * (p + 3));
        float v0 = g_v[(p + 0) * NF + lane];
        float v1 = g_v[(p + 1) * NF + lane];
        float v2 = g_v[(p + 2) * NF + lane];
        float v3 = g_v[(p + 3) * NF + lane];
        tf0 += r0.x * v0 + r2.x * v2;  u0 += r1.x * v1 + r3.x * v3;
        tf1 += r0.y * v0 + r2.y * v2;  u1 += r1.y * v1 + r3.y * v3;
        tf2 += r0.z * v0 + r2.z * v2;  u2 += r1.z * v1 + r3.z * v3;
        tf3 += r0.w * v0 + r2.w * v2;  u3 += r1.w * v1 + r3.w * v3;
    }
    for (; p < sege; p++) {
        float4 r = *reinterpret_cast<const float4*>(rhats + 4 * p);
        float v = g_v[p * NF + lane];
        tf0 += r.x * v; tf1 += r.y * v; tf2 += r.z * v; tf3 += r.w * v;
    }
    tf0 += u0; tf1 += u1; tf2 += u2; tf3 += u3;

    // invariants: x0 = l=0 scalar, x1 = |l=1 vector|^2
    float x0 = tf0;
    float x1 = tf1 * tf1 + tf2 * tf2 + tf3 * tf3;

    // GroupNorm: group == the 32 lanes of this warp
    float s0 = x0, s1 = x1;
#pragma unroll
    for (int off = 16; off; off >>= 1) {
        s0 += __shfl_xor_sync(FULL, s0, off);
        s1 += __shfl_xor_sync(FULL, s1, off);
    }
    float m0 = s0 * (1.f / 32.f), m1 = s1 * (1.f / 32.f);
    float d0 = x0 - m0, d1 = x1 - m1;
    float q0 = d0 * d0, q1 = d1 * d1;
#pragma unroll
    for (int off = 16; off; off >>= 1) {
        q0 += __shfl_xor_sync(FULL, q0, off);
        q1 += __shfl_xor_sync(FULL, q1, off);
    }
    float var0 = q0 * (1.f / 32.f), var1 = q1 * (1.f / 32.f);
    float xn0 = d0 * rsqrtf(var0 + GN_EPS) * gnw[lane]      + gnb[lane];
    float xn1 = d1 * rsqrtf(var1 + GN_EPS) * gnw[32 + lane] + gnb[32 + lane];

    // mixing
    float acc = 0.f;
#pragma unroll
    for (int o = 0; o < 32; o++) {
        float a0 = __shfl_sync(FULL, xn0, o);
        float a1 = __shfl_sync(FULL, xn1, o);
        acc += a0 * mixW[(o * 2 + 0) * 32 + lane]
             + a1 * mixW[(o * 2 + 1) * 32 + lane];
    }

    // self interaction
    const float* frow = feat + a * NF;
    const float* wrow = selfW + lane * NF;
    float sp = selfB[lane];
#pragma unroll
    for (int f = 0; f < NF; f++) sp += frow[f] * wrow[f];

    out[a * NF + lane] = acc + sp;
}

extern "C" void kernel_launch(void* const* d_in, const int* in_sizes, int n_in,
                              void* d_out, int out_size) {
    const float* in_features = (const float*)d_in[0];
    const float* tensor_rhats = (const float*)d_in[1];
    const float* dist_pairs   = (const float*)d_in[2];
    const float* int_weights  = (const float*)d_in[3];
    const float* selfint_w    = (const float*)d_in[4];
    const float* selfint_b    = (const float*)d_in[5];
    const float* mixing_w     = (const float*)d_in[6];
    const float* gn_weight    = (const float*)d_in[7];
    const float* gn_bias      = (const float*)d_in[8];
    const float* sens_mu      = (const float*)d_in[9];
    const float* sens_sigma   = (const float*)d_in[10];
    const int*   pair_first   = (const int*)d_in[11];
    const int*   pair_second  = (const int*)d_in[12];
    float* out = (float*)d_out;

    k0_prep<<<64 + 2 * ((N_PAIRS + 255) / 256), 256>>>(int_weights, pair_first,
                                                       dist_pairs, sens_mu, sens_sigma);
    k1_precompute<<<((N_ATOMS / 4) * 128 + 255) / 256, 256>>>(in_features);
    kv_pairs<<<(N_PAIRS * 32 + 255) / 256, 256>>>(pair_second);
    {
        int threads = 128;                 // 4 warps/block, 1 warp per atom
        int blocks = (N_ATOMS * 32 + threads - 1) / threads;
        k2_atoms<<<blocks, threads>>>(in_features, tensor_rhats,
                                      selfint_w, selfint_b, mixing_w,
                                      gn_weight, gn_bias, out);
    }
}

// round 14
// speedup vs baseline: 2.0274x; 1.6651x over previous
#include <cuda_runtime.h>
#include <cuda_fp16.h>

#define N_ATOMS 8000
#define N_PAIRS 80000
#define NF 32
#define N_DIST 16
#define S (N_DIST * NF)          // 512
#define GN_EPS 1e-5f
#define HARD_CUT 6.5f

// A[a][o][d] in fp16: 8.2 MB, L2-resident.  Half index: a*512 + o*16 + d.
__device__ __half g_Ah[N_ATOMS * S];
// Transposed weights: Wt2[f][o*16+d] = W[d][o][f]  (64 KB fp32)
__device__ float g_Wt2[NF * S];
// Transposed self-interaction weights: selfWt[f][o] = selfW[o][f]  (4 KB)
__device__ float g_selfWt[NF * NF];
// Precomputed sensitivities, fp16: senseh[p*16 + d]  (2.5 MB)
__device__ __half g_senseh[N_PAIRS * N_DIST];
// Per-pair channel vector v[p][o]  (10 MB fp32)
__device__ float g_v[N_PAIRS * NF];
// Segment starts: pairs for atom a are [g_seg[a], g_seg[a+1])
__device__ int g_seg[N_ATOMS + 1];

// Merged light prep:
//  blocks [0,64): transpose W -> Wt2 (block 0 also transposes selfW)
//  [64,377): seg;  [377,690): sense (fp16)
__global__ void k0_prep(const float* __restrict__ W, const float* __restrict__ selfW,
                        const int* __restrict__ pf,
                        const float* __restrict__ dist,
                        const float* __restrict__ mu, const float* __restrict__ sigma) {
    int b = blockIdx.x;
    if (b < 64) {
        int idx = b * 256 + threadIdx.x;            // over S*NF = 16384
        int d = idx & 15;
        int o = (idx >> 4) & 31;
        int f = idx >> 9;
        g_Wt2[idx] = W[(d * NF + o) * NF + f];
        if (b < 4) {                                 // 4*256 = 1024 = NF*NF
            int i = b * 256 + threadIdx.x;
            int oo = i & 31, ff = i >> 5;
            g_selfWt[ff * NF + oo] = selfW[oo * NF + ff];
        }
    } else if (b < 64 + 313) {
        int p = (b - 64) * 256 + threadIdx.x;
        if (p >= N_PAIRS) return;
        int cur = pf[p];
        int prev = (p == 0) ? -1 : pf[p - 1];
        for (int x = prev + 1; x <= cur; x++) g_seg[x] = p;
        if (p == N_PAIRS - 1)
            for (int x = cur + 1; x <= N_ATOMS; x++) g_seg[x] = N_PAIRS;
    } else {
        int p = (b - 377) * 256 + threadIdx.x;
        if (p >= N_PAIRS) return;
        float dd  = dist[p];
        float inv = 1.f / dd;
        float c   = __cosf(dd * (float)(3.14159265358979323846 / (2.0 * 6.5)));
        float cut = (dd < HARD_CUT) ? c * c : 0.f;
        __half2* outp = reinterpret_cast<__half2*>(g_senseh + p * N_DIST);
#pragma unroll
        for (int q = 0; q < 4; q++) {
            float z0 = (inv - mu[4 * q + 0]) / sigma[4 * q + 0];
            float z1 = (inv - mu[4 * q + 1]) / sigma[4 * q + 1];
            float z2 = (inv - mu[4 * q + 2]) / sigma[4 * q + 2];
            float z3 = (inv - mu[4 * q + 3]) / sigma[4 * q + 3];
            float r0 = __expf(-0.5f * z0 * z0) * cut;
            float r1 = __expf(-0.5f * z1 * z1) * cut;
            float r2 = __expf(-0.5f * z2 * z2) * cut;
            float r3 = __expf(-0.5f * z3 * z3) * cut;
            outp[q * 2 + 0] = __floats2half2_rn(r0, r1);
            outp[q * 2 + 1] = __floats2half2_rn(r2, r3);
        }
    }
}

// k1: A[a][o][d] = sum_f feat[a,f] * W[d,o,f], 4 atoms per thread.
__global__ void __launch_bounds__(256)
k1_precompute(const float* __restrict__ feat) {
    int idx = blockIdx.x * blockDim.x + threadIdx.x;   // over (N_ATOMS/4)*128
    if (idx >= (N_ATOMS / 4) * 128) return;
    int a0 = (idx >> 7) * 4;
    int e4 = idx & 127;
    const float4* feat4 = reinterpret_cast<const float4*>(feat);
    const float4* Wt4   = reinterpret_cast<const float4*>(g_Wt2);
    float4 acc0 = make_float4(0.f, 0.f, 0.f, 0.f);
    float4 acc1 = acc0, acc2 = acc0, acc3 = acc0;
#pragma unroll
    for (int f4 = 0; f4 < 8; f4++) {
        float4 w0 = Wt4[(4 * f4 + 0) * 128 + e4];
        float4 w1 = Wt4[(4 * f4 + 1) * 128 + e4];
        float4 w2 = Wt4[(4 * f4 + 2) * 128 + e4];
        float4 w3 = Wt4[(4 * f4 + 3) * 128 + e4];
        float4 fr0 = feat4[(a0 + 0) * 8 + f4];
        float4 fr1 = feat4[(a0 + 1) * 8 + f4];
        float4 fr2 = feat4[(a0 + 2) * 8 + f4];
        float4 fr3 = feat4[(a0 + 3) * 8 + f4];
        acc0.x += fr0.x * w0.x + fr0.y * w1.x + fr0.z * w2.x + fr0.w * w3.x;
        acc0.y += fr0.x * w0.y + fr0.y * w1.y + fr0.z * w2.y + fr0.w * w3.y;
        acc0.z += fr0.x * w0.z + fr0.y * w1.z + fr0.z * w2.z + fr0.w * w3.z;
        acc0.w += fr0.x * w0.w + fr0.y * w1.w + fr0.z * w2.w + fr0.w * w3.w;
        acc1.x += fr1.x * w0.x + fr1.y * w1.x + fr1.z * w2.x + fr1.w * w3.x;
        acc1.y += fr1.x * w0.y + fr1.y * w1.y + fr1.z * w2.y + fr1.w * w3.y;
        acc1.z += fr1.x * w0.z + fr1.y * w1.z + fr1.z * w2.z + fr1.w * w3.z;
        acc1.w += fr1.x * w0.w + fr1.y * w1.w + fr1.z * w2.w + fr1.w * w3.w;
        acc2.x += fr2.x * w0.x + fr2.y * w1.x + fr2.z * w2.x + fr2.w * w3.x;
        acc2.y += fr2.x * w0.y + fr2.y * w1.y + fr2.z * w2.y + fr2.w * w3.y;
        acc2.z += fr2.x * w0.z + fr2.y * w1.z + fr2.z * w2.z + fr2.w * w3.z;
        acc2.w += fr2.x * w0.w + fr2.y * w1.w + fr2.z * w2.w + fr2.w * w3.w;
        acc3.x += fr3.x * w0.x + fr3.y * w1.x + fr3.z * w2.x + fr3.w * w3.x;
        acc3.y += fr3.x * w0.y + fr3.y * w1.y + fr3.z * w2.y + fr3.w * w3.y;
        acc3.z += fr3.x * w0.z + fr3.y * w1.z + fr3.z * w2.z + fr3.w * w3.z;
        acc3.w += fr3.x * w0.w + fr3.y * w1.w + fr3.z * w2.w + fr3.w * w3.w;
    }
    __half2* o0 = reinterpret_cast<__half2*>(g_Ah + (a0 + 0) * S + e4 * 4);
    __half2* o1 = reinterpret_cast<__half2*>(g_Ah + (a0 + 1) * S + e4 * 4);
    __half2* o2 = reinterpret_cast<__half2*>(g_Ah + (a0 + 2) * S + e4 * 4);
    __half2* o3 = reinterpret_cast<__half2*>(g_Ah + (a0 + 3) * S + e4 * 4);
    o0[0] = __floats2half2_rn(acc0.x, acc0.y); o0[1] = __floats2half2_rn(acc0.z, acc0.w);
    o1[0] = __floats2half2_rn(acc1.x, acc1.y); o1[1] = __floats2half2_rn(acc1.z, acc1.w);
    o2[0] = __floats2half2_rn(acc2.x, acc2.y); o2[1] = __floats2half2_rn(acc2.z, acc2.w);
    o3[0] = __floats2half2_rn(acc3.x, acc3.y); o3[1] = __floats2half2_rn(acc3.z, acc3.w);
}

// kv: one warp per pair.  v[p][o] = sum_d sense[p,d] * A[j][o][d].
__global__ void __launch_bounds__(256)
kv_pairs(const int* __restrict__ ps) {
    const unsigned FULL = 0xffffffffu;
    int p = (blockIdx.x * blockDim.x + threadIdx.x) >> 5;
    int lane = threadIdx.x & 31;
    if (p >= N_PAIRS) return;

    int j = ps[p];                                   // uniform broadcast
    const float4* Ap = reinterpret_cast<const float4*>(g_Ah + j * S);
    float4 ha = Ap[lane];        // lanes cover first 512B contiguously
    float4 hb = Ap[32 + lane];   // second 512B
    float4 sh = reinterpret_cast<const float4*>(g_senseh + p * N_DIST)[lane & 1];

    const __half2* sv = reinterpret_cast<const __half2*>(&sh);
    float2 s0 = __half22float2(sv[0]);
    float2 s1 = __half22float2(sv[1]);
    float2 s2 = __half22float2(sv[2]);
    float2 s3 = __half22float2(sv[3]);

    const __half2* av = reinterpret_cast<const __half2*>(&ha);
    float2 a0 = __half22float2(av[0]);
    float2 a1 = __half22float2(av[1]);
    float2 a2 = __half22float2(av[2]);
    float2 a3 = __half22float2(av[3]);
    const __half2* bv = reinterpret_cast<const __half2*>(&hb);
    float2 b0 = __half22float2(bv[0]);
    float2 b1 = __half22float2(bv[1]);
    float2 b2 = __half22float2(bv[2]);
    float2 b3 = __half22float2(bv[3]);

    float p1 = s0.x * a0.x + s0.y * a0.y + s1.x * a1.x + s1.y * a1.y
             + s2.x * a2.x + s2.y * a2.y + s3.x * a3.x + s3.y * a3.y;
    float p2 = s0.x * b0.x + s0.y * b0.y + s1.x * b1.x + s1.y * b1.y
             + s2.x * b2.x + s2.y * b2.y + s3.x * b3.x + s3.y * b3.y;

    float v1 = p1 + __shfl_xor_sync(FULL, p1, 1);    // lanes 2c,2c+1: v[c]
    float v2 = p2 + __shfl_xor_sync(FULL, p2, 1);    // lanes 2c,2c+1: v[16+c]
    int src = (2 * lane) & 31;
    float w1 = __shfl_sync(FULL, v1, src);
    float w2 = __shfl_sync(FULL, v2, src);
    float v = (lane < 16) ? w1 : w2;                 // v[lane]

    g_v[p * NF + lane] = v;                          // coalesced 128B store
}

// katoms: warp per atom.  Segment loop reads v[p][lane] contiguous, independent.
__global__ void __launch_bounds__(128)
k2_atoms(const float* __restrict__ feat,
         const float* __restrict__ rhats,
         const float* __restrict__ selfB,
         const float* __restrict__ mixW,
         const float* __restrict__ gnw,
         const float* __restrict__ gnb,
         float* __restrict__ out) {
    const unsigned FULL = 0xffffffffu;
    int warp = (blockIdx.x * blockDim.x + threadIdx.x) >> 5;
    int lane = threadIdx.x & 31;
    if (warp >= N_ATOMS) return;
    const int a = warp;

    const int segs = g_seg[a];
    const int sege = g_seg[a + 1];

    float tf0 = 0.f, tf1 = 0.f, tf2 = 0.f, tf3 = 0.f;
    float u0 = 0.f, u1 = 0.f, u2 = 0.f, u3 = 0.f;

    int p = segs;
    for (; p + 4 <= sege; p += 4) {
        float4 r0 = *reinterpret_cast<const float4*>(rhats + 4 * (p + 0));
        float4 r1 = *reinterpret_cast<const float4*>(rhats + 4 * (p + 1));
        float4 r2 = *reinterpret_cast<const float4*>(rhats + 4 * (p + 2));
        float4 r3 = *reinterpret_cast<const float4*>(rhats + 4 * (p + 3));
        float v0 = g_v[(p + 0) * NF + lane];
        float v1 = g_v[(p + 1) * NF + lane];
        float v2 = g_v[(p + 2) * NF + lane];
        float v3 = g_v[(p + 3) * NF + lane];
        tf0 += r0.x * v0 + r2.x * v2;  u0 += r1.x * v1 + r3.x * v3;
        tf1 += r0.y * v0 + r2.y * v2;  u1 += r1.y * v1 + r3.y * v3;
        tf2 += r0.z * v0 + r2.z * v2;  u2 += r1.z * v1 + r3.z * v3;
        tf3 += r0.w * v0 + r2.w * v2;  u3 += r1.w * v1 + r3.w * v3;
    }
    for (; p < sege; p++) {
        float4 r = *reinterpret_cast<const float4*>(rhats + 4 * p);
        float v = g_v[p * NF + lane];
        tf0 += r.x * v; tf1 += r.y * v; tf2 += r.z * v; tf3 += r.w * v;
    }
    tf0 += u0; tf1 += u1; tf2 += u2; tf3 += u3;

    // invariants: x0 = l=0 scalar, x1 = |l=1 vector|^2
    float x0 = tf0;
    float x1 = tf1 * tf1 + tf2 * tf2 + tf3 * tf3;

    // GroupNorm: group == the 32 lanes of this warp
    float s0 = x0, s1 = x1;
#pragma unroll
    for (int off = 16; off; off >>= 1) {
        s0 += __shfl_xor_sync(FULL, s0, off);
        s1 += __shfl_xor_sync(FULL, s1, off);
    }
    float m0 = s0 * (1.f / 32.f), m1 = s1 * (1.f / 32.f);
    float d0 = x0 - m0, d1 = x1 - m1;
    float q0 = d0 * d0, q1 = d1 * d1;
#pragma unroll
    for (int off = 16; off; off >>= 1) {
        q0 += __shfl_xor_sync(FULL, q0, off);
        q1 += __shfl_xor_sync(FULL, q1, off);
    }
    float var0 = q0 * (1.f / 32.f), var1 = q1 * (1.f / 32.f);
    float xn0 = d0 * rsqrtf(var0 + GN_EPS) * gnw[lane]      + gnb[lane];
    float xn1 = d1 * rsqrtf(var1 + GN_EPS) * gnw[32 + lane] + gnb[32 + lane];

    // mixing
    float acc = 0.f;
#pragma unroll
    for (int o = 0; o < 32; o++) {
        float a0 = __shfl_sync(FULL, xn0, o);
        float a1 = __shfl_sync(FULL, xn1, o);
        acc += a0 * mixW[(o * 2 + 0) * 32 + lane]
             + a1 * mixW[(o * 2 + 1) * 32 + lane];
    }

    // self interaction: coalesced via transposed weights.
    // frow[f] is a warp-uniform broadcast; selfWt row is lane-consecutive.
    const float* frow = feat + a * NF;
    float sp = selfB[lane];
#pragma unroll
    for (int f = 0; f < NF; f++) sp += frow[f] * g_selfWt[f * NF + lane];

    out[a * NF + lane] = acc + sp;
}

extern "C" void kernel_launch(void* const* d_in, const int* in_sizes, int n_in,
                              void* d_out, int out_size) {
    const float* in_features = (const float*)d_in[0];
    const float* tensor_rhats = (const float*)d_in[1];
    const float* dist_pairs   = (const float*)d_in[2];
    const float* int_weights  = (const float*)d_in[3];
    const float* selfint_w    = (const float*)d_in[4];
    const float* selfint_b    = (const float*)d_in[5];
    const float* mixing_w     = (const float*)d_in[6];
    const float* gn_weight    = (const float*)d_in[7];
    const float* gn_bias      = (const float*)d_in[8];
    const float* sens_mu      = (const float*)d_in[9];
    const float* sens_sigma   = (const float*)d_in[10];
    const int*   pair_first   = (const int*)d_in[11];
    const int*   pair_second  = (const int*)d_in[12];
    float* out = (float*)d_out;

    k0_prep<<<64 + 2 * ((N_PAIRS + 255) / 256), 256>>>(int_weights, selfint_w,
                                                       pair_first, dist_pairs,
                                                       sens_mu, sens_sigma);
    k1_precompute<<<((N_ATOMS / 4) * 128 + 255) / 256, 256>>>(in_features);
    kv_pairs<<<(N_PAIRS * 32 + 255) / 256, 256>>>(pair_second);
    {
        int threads = 128;                 // 4 warps/block, 1 warp per atom
        int blocks = (N_ATOMS * 32 + threads - 1) / threads;
        k2_atoms<<<blocks, threads>>>(in_features, tensor_rhats,
                                      selfint_b, mixing_w,
                                      gn_weight, gn_bias, out);
    }
}